// round 2
// baseline (speedup 1.0000x reference)
#include <cuda_runtime.h>

#define N_NODES 100000
#define D 64
#define N_EDGES 1250000
#define NPB 64  // nodes per block in the fused GEMM

// ---------------------------------------------------------------------------
// Kernel 1: zero the aggregation scratch (we reuse d_out as aggr buffer).
// ---------------------------------------------------------------------------
__global__ void zero_kernel(float4* __restrict__ p, int n4) {
    int i = blockIdx.x * blockDim.x + threadIdx.x;
    if (i < n4) p[i] = make_float4(0.f, 0.f, 0.f, 0.f);
}

// ---------------------------------------------------------------------------
// Kernel 2: edge scatter. 16 threads per edge, each handles one float4 chunk
// of the 64-float row: aggr[dst] += x[src], via red.global.add.v4.f32.
// Runtime-detects whether edge_index is int64 or int32 (JAX x64 ambiguity).
// ---------------------------------------------------------------------------
__global__ void scatter_kernel(const float* __restrict__ x,
                               const int* __restrict__ e32,
                               float* __restrict__ aggr) {
    int t = blockIdx.x * blockDim.x + threadIdx.x;
    int e = t >> 4;
    if (e >= N_EDGES) return;
    int c = (t & 15) << 2;  // float offset within row (0,4,...,60)

    // Detect int64 vs int32 edge_index: node ids are < 2^31 and nonnegative,
    // so for int64 (little-endian) the odd 32-bit words are all zero. These
    // probe loads are uniform across the grid -> L2 broadcast, negligible.
    bool is64 = (e32[1] == 0) && (e32[3] == 0) && (e32[5] == 0) && (e32[7] == 0);

    int src, dst;
    if (is64) {
        src = e32[2 * e];                   // low word
        dst = e32[2 * (N_EDGES + e)];
    } else {
        src = e32[e];
        dst = e32[N_EDGES + e];
    }

    float4 v = *reinterpret_cast<const float4*>(x + (long long)src * D + c);
    float* p = aggr + (long long)dst * D + c;
    asm volatile("red.global.add.v4.f32 [%0], {%1,%2,%3,%4};"
                 :: "l"(p), "f"(v.x), "f"(v.y), "f"(v.z), "f"(v.w)
                 : "memory");
}

// ---------------------------------------------------------------------------
// Kernel 3: fused  out = tanh( [aggr | x] @ [W_l ; W_r] + b )  per node.
// aggr is read from d_out (scratch), result written in place (safe: each
// block stages its own rows into smem before writing).
//
// Block: 256 threads. Each thread computes 4 nodes x 4 cols (float4 accum).
// Shared: combined W (128x64 f32, 32KB) + staged [aggr|x] rows (64x128 f32,
// 32KB) + bias (256B)  => 65792 B dynamic smem.
// ---------------------------------------------------------------------------
__global__ void fused_gemm_kernel(const float* __restrict__ x,
                                  const float* __restrict__ Wl,
                                  const float* __restrict__ bl,
                                  const float* __restrict__ Wr,
                                  float* __restrict__ out /* aggr in, result out */) {
    extern __shared__ float sm[];
    float* sW  = sm;                 // [128][64] : rows 0..63 = W_l, 64..127 = W_r
    float* sAX = sm + 128 * 64;      // [NPB][128]: cols 0..63 = aggr, 64..127 = x
    float* sB  = sAX + NPB * 128;    // [64]

    int tid = threadIdx.x;
    int node0 = blockIdx.x * NPB;

    // --- stage weights (flat copy: row-major layout is identical) ---
    float4* sW4 = reinterpret_cast<float4*>(sW);
    const float4* Wl4 = reinterpret_cast<const float4*>(Wl);
    const float4* Wr4 = reinterpret_cast<const float4*>(Wr);
#pragma unroll
    for (int i = 0; i < 4; i++) {
        int idx = tid + i * 256;                 // 1024 float4 = 64x64 f32
        sW4[idx]        = Wl4[idx];
        sW4[1024 + idx] = Wr4[idx];
    }
    if (tid < 64) sB[tid] = bl[tid];

    // --- stage [aggr | x] rows: NPB nodes * 32 float4 each ---
    float4* sAX4 = reinterpret_cast<float4*>(sAX);
    for (int i = tid; i < NPB * 32; i += 256) {
        int n = i >> 5;       // node within block
        int c = i & 31;       // float4 index within 128-float row
        int node = node0 + n;
        float4 v = make_float4(0.f, 0.f, 0.f, 0.f);
        if (node < N_NODES) {
            if (c < 16) v = *reinterpret_cast<const float4*>(out + (long long)node * D + c * 4);
            else        v = *reinterpret_cast<const float4*>(x   + (long long)node * D + (c - 16) * 4);
        }
        sAX4[i] = v;
    }
    __syncthreads();

    // --- compute: thread (tx, ng) does cols [tx*4, tx*4+4) of nodes ng*4..+3 ---
    int tx = tid & 15;
    int ng = tid >> 4;

    float4 bb = reinterpret_cast<float4*>(sB)[tx];
    float4 acc0 = bb, acc1 = bb, acc2 = bb, acc3 = bb;

    const float* r0 = sAX + (ng * 4 + 0) * 128;
    const float* r1 = sAX + (ng * 4 + 1) * 128;
    const float* r2 = sAX + (ng * 4 + 2) * 128;
    const float* r3 = sAX + (ng * 4 + 3) * 128;

#pragma unroll 8
    for (int k = 0; k < 128; k++) {
        float4 w = sW4[k * 16 + tx];
        float a0 = r0[k], a1 = r1[k], a2 = r2[k], a3 = r3[k];
        acc0.x += a0 * w.x; acc0.y += a0 * w.y; acc0.z += a0 * w.z; acc0.w += a0 * w.w;
        acc1.x += a1 * w.x; acc1.y += a1 * w.y; acc1.z += a1 * w.z; acc1.w += a1 * w.w;
        acc2.x += a2 * w.x; acc2.y += a2 * w.y; acc2.z += a2 * w.z; acc2.w += a2 * w.w;
        acc3.x += a3 * w.x; acc3.y += a3 * w.y; acc3.z += a3 * w.z; acc3.w += a3 * w.w;
    }

    // --- tanh + store (in place over the aggr scratch) ---
    float4 accs[4] = {acc0, acc1, acc2, acc3};
#pragma unroll
    for (int n = 0; n < 4; n++) {
        int node = node0 + ng * 4 + n;
        if (node < N_NODES) {
            float4 a = accs[n];
            a.x = tanhf(a.x); a.y = tanhf(a.y); a.z = tanhf(a.z); a.w = tanhf(a.w);
            *reinterpret_cast<float4*>(out + (long long)node * D + tx * 4) = a;
        }
    }
}

// ---------------------------------------------------------------------------
extern "C" void kernel_launch(void* const* d_in, const int* in_sizes, int n_in,
                              void* d_out, int out_size) {
    const float* x  = (const float*)d_in[0];
    const int*   ei = (const int*)d_in[1];   // int32 or int64, detected on device
    const float* Wl = (const float*)d_in[2];
    const float* bl = (const float*)d_in[3];
    const float* Wr = (const float*)d_in[4];
    float* out = (float*)d_out;

    // 1) zero aggr scratch (= d_out)
    int n4 = N_NODES * D / 4;  // 1.6M float4
    zero_kernel<<<(n4 + 255) / 256, 256>>>((float4*)out, n4);

    // 2) edge scatter-add
    int threads = N_EDGES * 16;  // 20M threads, 16 per edge
    scatter_kernel<<<(threads + 255) / 256, 256>>>(x, ei, out);

    // 3) fused GEMM + bias + tanh (in place)
    const int smem = (128 * 64 + NPB * 128 + 64) * (int)sizeof(float);  // 65792 B
    static bool attr_set = false;
    if (!attr_set) {
        cudaFuncSetAttribute(fused_gemm_kernel,
                             cudaFuncAttributeMaxDynamicSharedMemorySize, smem);
        attr_set = true;
    }
    fused_gemm_kernel<<<(N_NODES + NPB - 1) / NPB, 256, smem>>>(x, Wl, bl, Wr, out);
}